// round 5
// baseline (speedup 1.0000x reference)
#include <cuda_runtime.h>
#include <cuda_bf16.h>
#include <cstdint>

// Problem constants
#define Bb 8
#define Nn 1024
#define Cc 768
#define Hh 12
#define Dd 64
#define BHn (Bb*Hh)      // 96
#define Mr  (Bb*Nn)      // 8192

#define OUT_ELEMS  (Mr*Cc)                     // 6,291,456
#define ATTN_ELEMS ((long long)BHn*Nn*Nn)      // 100,663,296

// Scratch (static device arrays: allocation-free). Aligned for float4.
__device__ __align__(256) float g_q[BHn*Nn*Dd];
__device__ __align__(256) float g_k[BHn*Nn*Dd];
__device__ __align__(256) float g_v[BHn*Nn*Dd];
__device__ __align__(256) float g_ho[Mr*Cc];

// ---------------------------------------------------------------------------
// GEMM: C[M, NC] = A[M,768] @ W[768, NC]  (64x64 tile, 256 thr, 4x4 microtile)
// SCATTER mode: A = Ain (x), NC=2304, scatter cols into g_q/g_k/g_v [b,h,n,d]
// PROJ mode:    A = g_ho (resolved IN DEVICE CODE), NC=768, +bias, -> out
// ---------------------------------------------------------------------------
template<int NC, bool SCATTER>
__global__ __launch_bounds__(256, 2)
void gemm_kernel(const float* __restrict__ Ain, const float* __restrict__ W,
                 const float* __restrict__ bias, float* __restrict__ Cout)
{
    // Device-side resolution of the A operand (never pass __device__ symbols
    // from host code — that was the R3 bug).
    const float* __restrict__ A = SCATTER ? Ain : (const float*)g_ho;

    __shared__ float XsT[16][68];   // k-major transposed A tile (padded)
    __shared__ float Ws[16][64];    // W tile

    const int tid = threadIdx.x;
    const int tx = tid & 15;        // col group
    const int ty = tid >> 4;        // row group
    const int row0 = blockIdx.y * 64;
    const int col0 = blockIdx.x * 64;

    const int lrow = tid >> 2;          // 0..63 (A row within tile)
    const int lk4  = (tid & 3) << 2;    // 0,4,8,12
    const int wk   = tid >> 4;          // 0..15
    const int wc4  = (tid & 15) << 2;   // 0..60

    float acc[4][4];
#pragma unroll
    for (int i = 0; i < 4; i++)
#pragma unroll
        for (int j = 0; j < 4; j++) acc[i][j] = 0.f;

    for (int kk = 0; kk < 768; kk += 16) {
        float4 xa = *(const float4*)&A[(size_t)(row0 + lrow) * 768 + kk + lk4];
        XsT[lk4 + 0][lrow] = xa.x;
        XsT[lk4 + 1][lrow] = xa.y;
        XsT[lk4 + 2][lrow] = xa.z;
        XsT[lk4 + 3][lrow] = xa.w;
        *(float4*)&Ws[wk][wc4] =
            *(const float4*)&W[(size_t)(kk + wk) * NC + col0 + wc4];
        __syncthreads();
#pragma unroll
        for (int k = 0; k < 16; k++) {
            float4 a  = *(float4*)&XsT[k][ty << 2];
            float4 bv = *(float4*)&Ws[k][tx << 2];
            acc[0][0] += a.x * bv.x; acc[0][1] += a.x * bv.y;
            acc[0][2] += a.x * bv.z; acc[0][3] += a.x * bv.w;
            acc[1][0] += a.y * bv.x; acc[1][1] += a.y * bv.y;
            acc[1][2] += a.y * bv.z; acc[1][3] += a.y * bv.w;
            acc[2][0] += a.z * bv.x; acc[2][1] += a.z * bv.y;
            acc[2][2] += a.z * bv.z; acc[2][3] += a.z * bv.w;
            acc[3][0] += a.w * bv.x; acc[3][1] += a.w * bv.y;
            acc[3][2] += a.w * bv.z; acc[3][3] += a.w * bv.w;
        }
        __syncthreads();
    }

    if (SCATTER) {
        // whole 64-col tile lives in one (which, h) region (768 % 64 == 0)
        const int which = col0 / 768;
        const int h     = (col0 % 768) / 64;
        float* dst = (which == 0) ? g_q : ((which == 1) ? g_k : g_v);
#pragma unroll
        for (int i = 0; i < 4; i++) {
            const int r = row0 + (ty << 2) + i;
            const int b = r >> 10, n = r & 1023;
            float* p = dst + ((size_t)(b * Hh + h) * Nn + n) * Dd + (tx << 2);
            *(float4*)p = make_float4(acc[i][0], acc[i][1], acc[i][2], acc[i][3]);
        }
    } else {
        float4 bb = *(const float4*)&bias[col0 + (tx << 2)];
#pragma unroll
        for (int i = 0; i < 4; i++) {
            const int r = row0 + (ty << 2) + i;
            float4 v = make_float4(acc[i][0] + bb.x, acc[i][1] + bb.y,
                                   acc[i][2] + bb.z, acc[i][3] + bb.w);
            *(float4*)&Cout[(size_t)r * NC + col0 + (tx << 2)] = v;
        }
    }
}

// ---------------------------------------------------------------------------
// Fused attention, per (bh, 32-row tile), 512 threads, 48KB STATIC smem.
// Phase 1: S = Q K^T -> registers (p0/p1[8][4]; 2 rows/warp, lane owns 4 cols
//          of each 128-col chunk).
// Softmax in registers via warp shuffles; write normalized attn to gmem.
// Phase 2: O = P V. P chunk staged reg->smem; each lane owns 2 head-dim cols
//          (32 lanes x 2 = 64 = D). In-bounds by construction.
// smem union: phase1 {Qs[2048], Kst[64*132] @2048}
//             phase2 {Vs[8192] @0, Pch[32*128] @8192}  (12288 floats = 48KB)
// ---------------------------------------------------------------------------
__global__ __launch_bounds__(512, 1)
void attn_kernel(float* __restrict__ attn)   // may be nullptr
{
    __shared__ float sm[12288];  // exactly 48KB
    float* Qs  = sm;             // phase 1: [32][64]
    float* Kst = sm + 2048;      // phase 1: [64][132] (k-major transposed)
    float* Vs  = sm;             // phase 2: [128][64]
    float* Pch = sm + 8192;      // phase 2: [32][128]

    const int bh       = blockIdx.y;          // 0..95
    const int row_base = blockIdx.x * 32;     // 0..992
    const int tid  = threadIdx.x;
    const int lane = tid & 31;
    const int warp = tid >> 5;                // 0..15
    const int r0   = warp * 2;                // this warp's 2 local rows
    const float scale = 0.125f;               // 64^-0.5

    // load Q tile
    const float* qbase = g_q + ((size_t)bh * Nn + row_base) * Dd;
    for (int i = tid; i < 32 * 64; i += 512) Qs[i] = qbase[i];

    float p0[8][4], p1[8][4];   // scores rows r0,r0+1; col = ch*128 + lane*4 + t

    // ---------------- phase 1: scores into registers ----------------
#pragma unroll
    for (int ch = 0; ch < 8; ch++) {
        __syncthreads();   // Q visible (ch=0) / prior chunk's Kst reads done
        const float* kbase = g_k + ((size_t)bh * Nn + ch * 128) * Dd;
        for (int i = tid; i < 128 * 64; i += 512) {
            int c = i >> 6, k = i & 63;
            Kst[k * 132 + c] = kbase[i];
        }
        __syncthreads();

        float a00=0,a01=0,a02=0,a03=0, a10=0,a11=0,a12=0,a13=0;
#pragma unroll 16
        for (int k = 0; k < 64; k++) {
            float  q0 = Qs[r0 * 64 + k];
            float  q1 = Qs[(r0 + 1) * 64 + k];
            float4 kv = *(float4*)&Kst[k * 132 + (lane << 2)];   // <=127 ok
            a00 += q0 * kv.x; a01 += q0 * kv.y; a02 += q0 * kv.z; a03 += q0 * kv.w;
            a10 += q1 * kv.x; a11 += q1 * kv.y; a12 += q1 * kv.z; a13 += q1 * kv.w;
        }
        p0[ch][0]=a00; p0[ch][1]=a01; p0[ch][2]=a02; p0[ch][3]=a03;
        p1[ch][0]=a10; p1[ch][1]=a11; p1[ch][2]=a12; p1[ch][3]=a13;
    }

    // ---------------- softmax in registers ----------------
    float m0 = -1e30f, m1 = -1e30f;
#pragma unroll
    for (int ch = 0; ch < 8; ch++)
#pragma unroll
        for (int t = 0; t < 4; t++) {
            m0 = fmaxf(m0, p0[ch][t]);
            m1 = fmaxf(m1, p1[ch][t]);
        }
#pragma unroll
    for (int o = 16; o > 0; o >>= 1) {
        m0 = fmaxf(m0, __shfl_xor_sync(0xffffffffu, m0, o));
        m1 = fmaxf(m1, __shfl_xor_sync(0xffffffffu, m1, o));
    }
    float s0 = 0.f, s1 = 0.f;
#pragma unroll
    for (int ch = 0; ch < 8; ch++)
#pragma unroll
        for (int t = 0; t < 4; t++) {
            float e0 = __expf(scale * (p0[ch][t] - m0));
            float e1 = __expf(scale * (p1[ch][t] - m1));
            p0[ch][t] = e0; p1[ch][t] = e1;
            s0 += e0; s1 += e1;
        }
#pragma unroll
    for (int o = 16; o > 0; o >>= 1) {
        s0 += __shfl_xor_sync(0xffffffffu, s0, o);
        s1 += __shfl_xor_sync(0xffffffffu, s1, o);
    }
    const float i0 = 1.f / s0, i1 = 1.f / s1;
#pragma unroll
    for (int ch = 0; ch < 8; ch++)
#pragma unroll
        for (int t = 0; t < 4; t++) { p0[ch][t] *= i0; p1[ch][t] *= i1; }

    // write attn weights (coalesced float4 per lane)
    if (attn) {
        float* arow = attn + ((size_t)bh * Nn + row_base + r0) * (size_t)Nn;
#pragma unroll
        for (int ch = 0; ch < 8; ch++) {
            *(float4*)&arow[ch * 128 + (lane << 2)] =
                make_float4(p0[ch][0], p0[ch][1], p0[ch][2], p0[ch][3]);
            *(float4*)&arow[Nn + ch * 128 + (lane << 2)] =
                make_float4(p1[ch][0], p1[ch][1], p1[ch][2], p1[ch][3]);
        }
    }

    // ---------------- phase 2: O = P V  (lane owns 2 head-dim cols) ---------
    float2 o0 = make_float2(0.f, 0.f), o1 = make_float2(0.f, 0.f);
#pragma unroll
    for (int ch = 0; ch < 8; ch++) {
        __syncthreads();   // prior chunk reads done; (ch=0) phase-1 smem done
        const float* vbase = g_v + ((size_t)bh * Nn + ch * 128) * Dd;
        for (int i = tid; i < 128 * 64; i += 512) Vs[i] = vbase[i];
        // stage this warp's P chunk rows (register -> smem)
        *(float4*)&Pch[r0 * 128 + (lane << 2)] =
            make_float4(p0[ch][0], p0[ch][1], p0[ch][2], p0[ch][3]);
        *(float4*)&Pch[r0 * 128 + 128 + (lane << 2)] =
            make_float4(p1[ch][0], p1[ch][1], p1[ch][2], p1[ch][3]);
        __syncthreads();
#pragma unroll 8
        for (int j = 0; j < 128; j++) {
            float  sv0 = Pch[r0 * 128 + j];          // smem broadcast
            float  sv1 = Pch[r0 * 128 + 128 + j];
            float2 v2  = *(float2*)&Vs[j * 64 + (lane << 1)];   // <=62 ok
            o0.x += sv0 * v2.x; o0.y += sv0 * v2.y;
            o1.x += sv1 * v2.x; o1.y += sv1 * v2.y;
        }
    }

    const int b = bh / Hh, h = bh % Hh;
    float* ho = g_ho + ((size_t)(b * Nn + row_base + r0)) * Cc + h * 64 + (lane << 1);
    *(float2*)ho        = o0;
    *(float2*)(ho + Cc) = o1;
}

// ---------------------------------------------------------------------------
extern "C" void kernel_launch(void* const* d_in, const int* in_sizes, int n_in,
                              void* d_out, int out_size)
{
    const float* x      = (const float*)d_in[0];
    const float* w_qkv  = (const float*)d_in[1];
    const float* w_proj = (const float*)d_in[2];
    const float* b_proj = (const float*)d_in[3];

    float* out_ptr  = (float*)d_out;
    float* attn_ptr = nullptr;
    if ((long long)out_size >= (long long)OUT_ELEMS + ATTN_ELEMS)
        attn_ptr = out_ptr + OUT_ELEMS;

    // 1) QKV projection + scatter to [B,H,N,D]
    gemm_kernel<2304, true><<<dim3(2304 / 64, Mr / 64), 256>>>(
        x, w_qkv, nullptr, nullptr);

    // 2) fused attention (scores + softmax + attn write + PV), 48KB static smem
    attn_kernel<<<dim3(Nn / 32, BHn), 512>>>(attn_ptr);

    // 3) output projection + bias (A = g_ho resolved in device code)
    gemm_kernel<768, false><<<dim3(768 / 64, Mr / 64), 256>>>(
        nullptr, w_proj, b_proj, out_ptr);
}

// round 6
// speedup vs baseline: 2.8548x; 2.8548x over previous
#include <cuda_runtime.h>
#include <cuda_bf16.h>
#include <cstdint>

#define Bb 8
#define Nn 1024
#define Cc 768
#define Hh 12
#define Dd 64
#define BHn (Bb*Hh)      // 96
#define Mr  (Bb*Nn)      // 8192

#define OUT_ELEMS  (Mr*Cc)                     // 6,291,456
#define ATTN_ELEMS ((long long)BHn*Nn*Nn)      // 100,663,296

__device__ __align__(256) float g_q[BHn*Nn*Dd];
__device__ __align__(256) float g_k[BHn*Nn*Dd];
__device__ __align__(256) float g_v[BHn*Nn*Dd];
__device__ __align__(256) float g_ho[Mr*Cc];

// ---------------------------------------------------------------------------
// tf32 mma helpers (m16n8k8, row.col, fp32 accum)
// A frag: a0=(r,c) a1=(r+8,c) a2=(r,c+4) a3=(r+8,c+4), r=lane>>2, c=lane&3
// B frag: b0=(k,n)  b1=(k+4,n),  k=lane&3, n=lane>>2
// C frag: c0=(r,2c) c1=(r,2c+1) c2=(r+8,2c) c3=(r+8,2c+1)
// ---------------------------------------------------------------------------
__device__ __forceinline__ uint32_t f2tf(float x) {
    uint32_t r;
    asm("cvt.rna.tf32.f32 %0, %1;" : "=r"(r) : "f"(x));
    return r;
}
__device__ __forceinline__ void mma_tf32(float d[4], const uint32_t a[4],
                                         const uint32_t b0, const uint32_t b1) {
    asm volatile(
        "mma.sync.aligned.m16n8k8.row.col.f32.tf32.tf32.f32 "
        "{%0,%1,%2,%3}, {%4,%5,%6,%7}, {%8,%9}, {%0,%1,%2,%3};"
        : "+f"(d[0]), "+f"(d[1]), "+f"(d[2]), "+f"(d[3])
        : "r"(a[0]), "r"(a[1]), "r"(a[2]), "r"(a[3]), "r"(b0), "r"(b1));
}

// ---------------------------------------------------------------------------
// GEMM: C[M,NC] = A[M,768] @ W[768,NC], tf32 tensor cores.
// CTA tile 128x64, K-chunk 32. 8 warps in 4(m) x 2(n); warp tile 32x32.
// SCATTER: A=x, NC=2304, scatter to g_q/g_k/g_v.  PROJ: A=g_ho, +bias -> out.
// ---------------------------------------------------------------------------
#define AS_STRIDE 36
#define WS_STRIDE 72

template<int NC, bool SCATTER>
__global__ __launch_bounds__(256, 2)
void gemm_kernel(const float* __restrict__ Ain, const float* __restrict__ W,
                 const float* __restrict__ bias, float* __restrict__ Cout)
{
    const float* __restrict__ A = SCATTER ? Ain : (const float*)g_ho;

    __shared__ float As[128 * AS_STRIDE];   // [m][k] 128x32, pad->36
    __shared__ float Ws[32 * WS_STRIDE];    // [k][n] 32x64,  pad->72

    const int tid   = threadIdx.x;
    const int lane  = tid & 31;
    const int warp  = tid >> 5;           // 0..7
    const int mwarp = warp >> 1;          // 0..3
    const int nwarp = warp & 1;           // 0..1
    const int frow  = lane >> 2;          // 0..7
    const int fcol  = lane & 3;           // 0..3
    const int row0  = blockIdx.y * 128;
    const int col0  = blockIdx.x * 64;

    float acc[2][4][4];
#pragma unroll
    for (int i = 0; i < 2; i++)
#pragma unroll
        for (int j = 0; j < 4; j++)
#pragma unroll
            for (int t = 0; t < 4; t++) acc[i][j][t] = 0.f;

    for (int kk = 0; kk < 768; kk += 32) {
        // stage A tile: 1024 float4, 4 per thread
#pragma unroll
        for (int l = 0; l < 4; l++) {
            int fidx = tid + l * 256;
            int r = fidx >> 3, c4 = (fidx & 7) << 2;
            *(float4*)&As[r * AS_STRIDE + c4] =
                *(const float4*)&A[(size_t)(row0 + r) * 768 + kk + c4];
        }
        // stage W tile: 512 float4, 2 per thread
#pragma unroll
        for (int l = 0; l < 2; l++) {
            int fidx = tid + l * 256;
            int r = fidx >> 4, c4 = (fidx & 15) << 2;
            *(float4*)&Ws[r * WS_STRIDE + c4] =
                *(const float4*)&W[(size_t)(kk + r) * NC + col0 + c4];
        }
        __syncthreads();

#pragma unroll
        for (int ks = 0; ks < 4; ks++) {
            uint32_t a[2][4];
#pragma unroll
            for (int i = 0; i < 2; i++) {
                int rb = (mwarp * 32 + i * 16 + frow) * AS_STRIDE + ks * 8 + fcol;
                a[i][0] = f2tf(As[rb]);
                a[i][1] = f2tf(As[rb + 8 * AS_STRIDE]);
                a[i][2] = f2tf(As[rb + 4]);
                a[i][3] = f2tf(As[rb + 8 * AS_STRIDE + 4]);
            }
            uint32_t b0[4], b1[4];
#pragma unroll
            for (int j = 0; j < 4; j++) {
                int cb = (ks * 8 + fcol) * WS_STRIDE + nwarp * 32 + j * 8 + frow;
                b0[j] = f2tf(Ws[cb]);
                b1[j] = f2tf(Ws[cb + 4 * WS_STRIDE]);
            }
#pragma unroll
            for (int i = 0; i < 2; i++)
#pragma unroll
                for (int j = 0; j < 4; j++)
                    mma_tf32(acc[i][j], a[i], b0[j], b1[j]);
        }
        __syncthreads();
    }

    // epilogue
#pragma unroll
    for (int i = 0; i < 2; i++) {
        const int r = row0 + mwarp * 32 + i * 16 + frow;   // and r+8
#pragma unroll
        for (int j = 0; j < 4; j++) {
            const int cg = col0 + nwarp * 32 + j * 8 + fcol * 2;
            if (SCATTER) {
                const int which = cg / 768, rem = cg % 768;
                const int h = rem / 64, d = rem % 64;
                float* dst = (which == 0) ? g_q : ((which == 1) ? g_k : g_v);
                {
                    const int b = r >> 10, n = r & 1023;
                    float* p = dst + ((size_t)(b * Hh + h) * Nn + n) * Dd + d;
                    *(float2*)p = make_float2(acc[i][j][0], acc[i][j][1]);
                }
                {
                    const int r2 = r + 8;
                    const int b = r2 >> 10, n = r2 & 1023;
                    float* p = dst + ((size_t)(b * Hh + h) * Nn + n) * Dd + d;
                    *(float2*)p = make_float2(acc[i][j][2], acc[i][j][3]);
                }
            } else {
                float2 bb = *(const float2*)&bias[cg];
                *(float2*)&Cout[(size_t)r * NC + cg] =
                    make_float2(acc[i][j][0] + bb.x, acc[i][j][1] + bb.y);
                *(float2*)&Cout[(size_t)(r + 8) * NC + cg] =
                    make_float2(acc[i][j][2] + bb.x, acc[i][j][3] + bb.y);
            }
        }
    }
}

// ---------------------------------------------------------------------------
// Attention (tf32 mma), per (bh, 32 Q rows), 512 threads (16 warps).
// Warp grid 2(m) x 8(n). Phase 1: S(32x1024) into dyn smem via mma over D=64.
// Softmax per warp (2 rows), normalized P -> S smem + attn gmem.
// Phase 2: O(32x64) = P V via mma over 1024 keys, chunked 128.
// Dyn smem (floats): S[32*1028] | Qs[32*68] | KV[128*72]  = 44288 (173 KB)
// ---------------------------------------------------------------------------
#define S_STRIDE  1028
#define Q_STRIDE  68
#define KS_STRIDE 68
#define VS_STRIDE 72
#define SMEM_F (32*S_STRIDE + 32*Q_STRIDE + 128*VS_STRIDE)  // 44288
#define SMEM_B (SMEM_F * 4)                                 // 177152

__global__ __launch_bounds__(512, 1)
void attn_mma_kernel(float* __restrict__ attn)   // may be nullptr
{
    extern __shared__ float sm[];
    float* S  = sm;                        // [32][1028]
    float* Qs = sm + 32 * S_STRIDE;        // [32][68]
    float* KV = Qs + 32 * Q_STRIDE;        // [128][68 or 72]

    const int bh       = blockIdx.y;
    const int row_base = blockIdx.x * 32;
    const int tid   = threadIdx.x;
    const int lane  = tid & 31;
    const int warp  = tid >> 5;            // 0..15
    const int mwarp = warp >> 3;           // 0..1
    const int nwarp = warp & 7;            // 0..7
    const int frow  = lane >> 2;
    const int fcol  = lane & 3;
    const float scale = 0.125f;

    // stage Q (32x64): 512 float4, 1 per thread
    {
        const float* qb = g_q + ((size_t)bh * Nn + row_base) * Dd;
        int r = tid >> 4, c4 = (tid & 15) << 2;
        *(float4*)&Qs[r * Q_STRIDE + c4] = *(const float4*)&qb[r * 64 + c4];
    }
    __syncthreads();

    // Q A-frags for this warp's 16-row block, all 8 k-steps
    uint32_t qa[8][4];
#pragma unroll
    for (int ks = 0; ks < 8; ks++) {
        int rb = (mwarp * 16 + frow) * Q_STRIDE + ks * 8 + fcol;
        qa[ks][0] = f2tf(Qs[rb]);
        qa[ks][1] = f2tf(Qs[rb + 8 * Q_STRIDE]);
        qa[ks][2] = f2tf(Qs[rb + 4]);
        qa[ks][3] = f2tf(Qs[rb + 8 * Q_STRIDE + 4]);
    }

    // ---------------- phase 1: S = Q K^T ----------------
    for (int ch = 0; ch < 8; ch++) {
        __syncthreads();
        const float* kb = g_k + ((size_t)bh * Nn + ch * 128) * Dd;
#pragma unroll
        for (int l = 0; l < 4; l++) {
            int fidx = tid + l * 512;
            int r = fidx >> 4, c4 = (fidx & 15) << 2;
            *(float4*)&KV[r * KS_STRIDE + c4] = *(const float4*)&kb[r * 64 + c4];
        }
        __syncthreads();

        float sacc[2][4] = {{0,0,0,0},{0,0,0,0}};
#pragma unroll
        for (int ks = 0; ks < 8; ks++) {
#pragma unroll
            for (int j = 0; j < 2; j++) {
                int cb = (nwarp * 16 + j * 8 + frow) * KS_STRIDE + ks * 8 + fcol;
                uint32_t b0 = f2tf(KV[cb]);
                uint32_t b1 = f2tf(KV[cb + 4]);
                mma_tf32(sacc[j], qa[ks], b0, b1);
            }
        }
        // store C frags to S
#pragma unroll
        for (int j = 0; j < 2; j++) {
            int c = ch * 128 + nwarp * 16 + j * 8 + fcol * 2;
            int r = mwarp * 16 + frow;
            *(float2*)&S[r * S_STRIDE + c]       = make_float2(sacc[j][0], sacc[j][1]);
            *(float2*)&S[(r + 8) * S_STRIDE + c] = make_float2(sacc[j][2], sacc[j][3]);
        }
    }
    __syncthreads();

    // ---------------- softmax: warp w owns rows 2w, 2w+1 ----------------
#pragma unroll
    for (int rr = 0; rr < 2; rr++) {
        const int r = warp * 2 + rr;
        float4 vals[8];
        float m = -1e30f;
#pragma unroll
        for (int it = 0; it < 8; it++) {
            vals[it] = *(float4*)&S[r * S_STRIDE + it * 128 + lane * 4];
            m = fmaxf(m, fmaxf(fmaxf(vals[it].x, vals[it].y),
                               fmaxf(vals[it].z, vals[it].w)));
        }
#pragma unroll
        for (int o = 16; o > 0; o >>= 1)
            m = fmaxf(m, __shfl_xor_sync(0xffffffffu, m, o));
        float sum = 0.f;
#pragma unroll
        for (int it = 0; it < 8; it++) {
            vals[it].x = __expf(scale * (vals[it].x - m));
            vals[it].y = __expf(scale * (vals[it].y - m));
            vals[it].z = __expf(scale * (vals[it].z - m));
            vals[it].w = __expf(scale * (vals[it].w - m));
            sum += vals[it].x + vals[it].y + vals[it].z + vals[it].w;
        }
#pragma unroll
        for (int o = 16; o > 0; o >>= 1)
            sum += __shfl_xor_sync(0xffffffffu, sum, o);
        const float inv = 1.f / sum;
        float* arow = attn ? attn + ((size_t)bh * Nn + row_base + r) * (size_t)Nn
                           : nullptr;
#pragma unroll
        for (int it = 0; it < 8; it++) {
            float4 p = make_float4(vals[it].x * inv, vals[it].y * inv,
                                   vals[it].z * inv, vals[it].w * inv);
            *(float4*)&S[r * S_STRIDE + it * 128 + lane * 4] = p;
            if (arow) *(float4*)&arow[it * 128 + lane * 4] = p;
        }
    }
    __syncthreads();

    // ---------------- phase 2: O = P V ----------------
    float oacc[4] = {0, 0, 0, 0};
    for (int ch = 0; ch < 8; ch++) {
        __syncthreads();
        const float* vb = g_v + ((size_t)bh * Nn + ch * 128) * Dd;
#pragma unroll
        for (int l = 0; l < 4; l++) {
            int fidx = tid + l * 512;
            int r = fidx >> 4, c4 = (fidx & 15) << 2;
            *(float4*)&KV[r * VS_STRIDE + c4] = *(const float4*)&vb[r * 64 + c4];
        }
        __syncthreads();

#pragma unroll
        for (int ks = 0; ks < 16; ks++) {
            uint32_t a[4];
            int ab = (mwarp * 16 + frow) * S_STRIDE + ch * 128 + ks * 8 + fcol;
            a[0] = f2tf(S[ab]);
            a[1] = f2tf(S[ab + 8 * S_STRIDE]);
            a[2] = f2tf(S[ab + 4]);
            a[3] = f2tf(S[ab + 8 * S_STRIDE + 4]);
            int bb = (ks * 8 + fcol) * VS_STRIDE + nwarp * 8 + frow;
            uint32_t b0 = f2tf(KV[bb]);
            uint32_t b1 = f2tf(KV[bb + 4 * VS_STRIDE]);
            mma_tf32(oacc, a, b0, b1);
        }
    }

    // write O to g_ho
    {
        const int b = bh / Hh, h = bh % Hh;
        const int r = row_base + mwarp * 16 + frow;
        const int c = h * 64 + nwarp * 8 + fcol * 2;
        float* ho = g_ho + ((size_t)(b * Nn + r)) * Cc + c;
        *(float2*)ho             = make_float2(oacc[0], oacc[1]);
        *(float2*)(ho + 8 * Cc)  = make_float2(oacc[2], oacc[3]);
    }
}

// ---------------------------------------------------------------------------
extern "C" void kernel_launch(void* const* d_in, const int* in_sizes, int n_in,
                              void* d_out, int out_size)
{
    const float* x      = (const float*)d_in[0];
    const float* w_qkv  = (const float*)d_in[1];
    const float* w_proj = (const float*)d_in[2];
    const float* b_proj = (const float*)d_in[3];

    float* out_ptr  = (float*)d_out;
    float* attn_ptr = nullptr;
    if ((long long)out_size >= (long long)OUT_ELEMS + ATTN_ELEMS)
        attn_ptr = out_ptr + OUT_ELEMS;

    cudaFuncSetAttribute(attn_mma_kernel,
                         cudaFuncAttributeMaxDynamicSharedMemorySize, SMEM_B);

    // 1) QKV projection + scatter
    gemm_kernel<2304, true><<<dim3(2304 / 64, Mr / 128), 256>>>(
        x, w_qkv, nullptr, nullptr);

    // 2) fused attention
    attn_mma_kernel<<<dim3(Nn / 32, BHn), 512, SMEM_B>>>(attn_ptr);

    // 3) output projection + bias (A = g_ho resolved device-side)
    gemm_kernel<768, false><<<dim3(768 / 64, Mr / 128), 256>>>(
        nullptr, w_proj, b_proj, out_ptr);
}